// round 2
// baseline (speedup 1.0000x reference)
#include <cuda_runtime.h>
#include <math.h>

// Problem constants (match reference)
#define BB 512
#define TT 128
#define DD 512
#define KK 256          // DD/2 rotation blocks
#define ALPHA 0.1f
#define EPSN 1e-5f

// Kernel config
#define GCTA 128        // CTAs
#define MPER 4          // batch elements per CTA (GCTA*MPER == BB)
#define NT 512          // threads per CTA: thread c owns A-column c
#define NW (NT / 32)    // 16 warps
#define AROWS 96        // rows of A cached in dynamic smem (96*512*4 = 192KB)

__device__ __forceinline__ unsigned long long packdup(float a) {
    unsigned long long r;
    asm("mov.b64 %0, {%1, %1};" : "=l"(r) : "f"(a));
    return r;
}
__device__ __forceinline__ void fma2(unsigned long long& d,
                                     unsigned long long a,
                                     unsigned long long b) {
    asm("fma.rn.f32x2 %0, %1, %2, %0;" : "+l"(d) : "l"(a), "l"(b));
}
__device__ __forceinline__ float2 unpack2(unsigned long long v) {
    float2 f;
    asm("mov.b64 {%0, %1}, %2;" : "=f"(f.x), "=f"(f.y) : "l"(v));
    return f;
}

__global__ void __launch_bounds__(NT, 1)
can_path_kernel(const float* __restrict__ dx_pi,   // [B,T,2]
                const float* __restrict__ z0,      // [B,D]
                const float* __restrict__ x0,      // [B,2]
                const float* __restrict__ omega,   // [K,2]
                const float* __restrict__ Ag,      // [D,D] (symmetric)
                const float* __restrict__ z0b,     // [D]
                float* __restrict__ out_z,         // [B,T,D]
                float* __restrict__ out_x)         // [B,T,2]
{
    extern __shared__ __align__(16) float As[];       // AROWS * DD

    __shared__ __align__(16) float zx_s[DD * MPER];   // [i][m] interleaved
    __shared__ float x_s[MPER][2];
    __shared__ float red_s[NW][8];
    __shared__ float dxt_s[8];
    __shared__ float scale_s;

    const int c    = threadIdx.x;        // column 0..511
    const int lane = c & 31;
    const int wid  = c >> 5;
    const int blk  = c >> 1;             // rotation block of this column
    const int odd  = c & 1;
    const int base = blockIdx.x * MPER;

    // ---- preload A[0:AROWS] into smem ----
    {
        const float4* src = (const float4*)Ag;
        float4* dst = (float4*)As;
        const int n4 = AROWS * DD / 4;
        for (int i = c; i < n4; i += NT) dst[i] = src[i];
    }

    const float om0 = omega[2 * blk];
    const float om1 = omega[2 * blk + 1];

    // ---- ||z0_base|| (rotation-invariant; reference's per-x norm equals it) ----
    {
        float a_own = z0b[c];
        float v = a_own * a_own;
        #pragma unroll
        for (int o = 16; o; o >>= 1) v += __shfl_xor_sync(0xFFFFFFFFu, v, o);
        if (lane == 0) red_s[wid][0] = v;
    }
    if (c < MPER * 2) x_s[c >> 1][c & 1] = x0[(base + (c >> 1)) * 2 + (c & 1)];
    __syncthreads();
    if (c == 0) {
        float s = 0.f;
        #pragma unroll
        for (int w = 0; w < NW; w++) s += red_s[w][0];
        scale_s = 1.0f / (sqrtf(s) + EPSN);
    }
    __syncthreads();

    const float p0 = z0b[2 * blk] * scale_s;
    const float p1 = z0b[2 * blk + 1] * scale_s;

    // carried z: thread c holds column c of each of its M batch rows
    float zc[MPER];
    #pragma unroll
    for (int m = 0; m < MPER; m++) zc[m] = z0[(base + m) * DD + c];

    const float* Acol = Ag + c;

    for (int t = 0; t < TT; t++) {
        // ---- phase 1: z(x)[c] for each m; share partner value via shuffle ----
        float u[MPER], part[MPER];
        #pragma unroll
        for (int m = 0; m < MPER; m++) {
            float th = fmaf(om0, x_s[m][0], om1 * x_s[m][1]);
            float s, cc;
            sincosf(th, &s, &cc);
            u[m] = odd ? fmaf(s, p0, cc * p1) : fmaf(cc, p0, -s * p1);
        }
        *(float4*)&zx_s[c * 4] = make_float4(u[0], u[1], u[2], u[3]);
        #pragma unroll
        for (int m = 0; m < MPER; m++)
            part[m] = __shfl_xor_sync(0xFFFFFFFFu, u[m], 1);
        __syncthreads();

        // ---- phase 2: w[m] = sum_i zx[m][i] * A[i][c]  (packed f32x2, m-pairs) ----
        unsigned long long acc01 = 0ull, acc23 = 0ull;

        #pragma unroll 2
        for (int i = 0; i < AROWS; i += 4) {
            float b0 = As[(i + 0) * DD + c];
            float b1 = As[(i + 1) * DD + c];
            float b2 = As[(i + 2) * DD + c];
            float b3 = As[(i + 3) * DD + c];
            ulonglong2 zz0 = *(const ulonglong2*)&zx_s[(i + 0) * 4];
            ulonglong2 zz1 = *(const ulonglong2*)&zx_s[(i + 1) * 4];
            ulonglong2 zz2 = *(const ulonglong2*)&zx_s[(i + 2) * 4];
            ulonglong2 zz3 = *(const ulonglong2*)&zx_s[(i + 3) * 4];
            unsigned long long d0 = packdup(b0), d1 = packdup(b1);
            unsigned long long d2 = packdup(b2), d3 = packdup(b3);
            fma2(acc01, zz0.x, d0); fma2(acc23, zz0.y, d0);
            fma2(acc01, zz1.x, d1); fma2(acc23, zz1.y, d1);
            fma2(acc01, zz2.x, d2); fma2(acc23, zz2.y, d2);
            fma2(acc01, zz3.x, d3); fma2(acc23, zz3.y, d3);
        }
        #pragma unroll 2
        for (int i = AROWS; i < DD; i += 4) {
            float b0 = __ldg(&Acol[(i + 0) * DD]);
            float b1 = __ldg(&Acol[(i + 1) * DD]);
            float b2 = __ldg(&Acol[(i + 2) * DD]);
            float b3 = __ldg(&Acol[(i + 3) * DD]);
            ulonglong2 zz0 = *(const ulonglong2*)&zx_s[(i + 0) * 4];
            ulonglong2 zz1 = *(const ulonglong2*)&zx_s[(i + 1) * 4];
            ulonglong2 zz2 = *(const ulonglong2*)&zx_s[(i + 2) * 4];
            ulonglong2 zz3 = *(const ulonglong2*)&zx_s[(i + 3) * 4];
            unsigned long long d0 = packdup(b0), d1 = packdup(b1);
            unsigned long long d2 = packdup(b2), d3 = packdup(b3);
            fma2(acc01, zz0.x, d0); fma2(acc23, zz0.y, d0);
            fma2(acc01, zz1.x, d1); fma2(acc23, zz1.y, d1);
            fma2(acc01, zz2.x, d2); fma2(acc23, zz2.y, d2);
            fma2(acc01, zz3.x, d3); fma2(acc23, zz3.y, d3);
        }

        float2 w01 = unpack2(acc01);
        float2 w23 = unpack2(acc23);
        float w[MPER] = {w01.x, w01.y, w23.x, w23.y};

        // ---- phase 3: per-column gradient term, reduce dx_can ----
        // g_k = zx[2k]*w[2k+1] - zx[2k+1]*w[2k]
        //  => column contribution h[c] = (odd ? +part : -part) * w[c]
        const float sgn = odd ? 1.0f : -1.0f;
        float r[8];
        #pragma unroll
        for (int m = 0; m < MPER; m++) {
            float h = sgn * part[m] * w[m];
            r[2 * m]     = om0 * h;
            r[2 * m + 1] = om1 * h;
        }
        #pragma unroll
        for (int j = 0; j < 8; j++) {
            #pragma unroll
            for (int o = 16; o; o >>= 1)
                r[j] += __shfl_xor_sync(0xFFFFFFFFu, r[j], o);
        }
        if (lane == 0) {
            #pragma unroll
            for (int j = 0; j < 8; j++) red_s[wid][j] = r[j];
        }
        __syncthreads();
        if (c < 8) {
            float s = 0.f;
            #pragma unroll
            for (int w2 = 0; w2 < NW; w2++) s += red_s[w2][c];
            const int m = c >> 1, j = c & 1;
            float dxt = dx_pi[((base + m) * TT + t) * 2 + j] + ALPHA * s;
            dxt_s[c] = dxt;
            float xn = x_s[m][j] + dxt;
            xn = fminf(fmaxf(xn, 0.0f), 2.0f);   // BOX_W == BOX_H == 2
            x_s[m][j] = xn;
            out_x[((base + m) * TT + t) * 2 + j] = xn;
        }
        __syncthreads();

        // ---- phase 4: carried z' = T(dx_total) z ; write outputs ----
        #pragma unroll
        for (int m = 0; m < MPER; m++) {
            float th2 = fmaf(om0, dxt_s[2 * m], om1 * dxt_s[2 * m + 1]);
            float s2, c2;
            sincosf(th2, &s2, &c2);
            float zp = __shfl_xor_sync(0xFFFFFFFFu, zc[m], 1);
            float zn = odd ? fmaf(s2, zp, c2 * zc[m])
                           : fmaf(c2, zc[m], -s2 * zp);
            zc[m] = zn;
            out_z[((size_t)(base + m) * TT + t) * DD + c] = zn;
        }
        // next phase-1 zx_s writes are ordered by the two reduction barriers
    }
}

extern "C" void kernel_launch(void* const* d_in, const int* in_sizes, int n_in,
                              void* d_out, int out_size) {
    (void)in_sizes; (void)n_in; (void)out_size;
    const float* dx_pi = (const float*)d_in[0];   // [512,128,2]
    const float* z0    = (const float*)d_in[1];   // [512,512]
    const float* x0    = (const float*)d_in[2];   // [512,2]
    const float* omega = (const float*)d_in[3];   // [256,2]
    const float* Ag    = (const float*)d_in[4];   // [512,512]
    const float* z0b   = (const float*)d_in[5];   // [512]

    float* out_z = (float*)d_out;                       // [512,128,512]
    float* out_x = out_z + (size_t)BB * TT * DD;        // [512,128,2]

    const size_t shmem = (size_t)AROWS * DD * sizeof(float);  // 192 KB
    cudaFuncSetAttribute(can_path_kernel,
                         cudaFuncAttributeMaxDynamicSharedMemorySize,
                         (int)shmem);
    can_path_kernel<<<GCTA, NT, shmem>>>(dx_pi, z0, x0, omega, Ag, z0b,
                                         out_z, out_x);
}

// round 3
// speedup vs baseline: 1.8270x; 1.8270x over previous
#include <cuda_runtime.h>
#include <math.h>
#include <stdint.h>

// Problem constants
#define BB 512
#define TT 128
#define DD 512
#define ALPHA 0.1f
#define EPSN 1e-5f

// Config: 64 clusters x 2 CTAs. Cluster handles 8 batch rows; CTA owns 256 cols.
#define CSZ 2
#define GCTA 128
#define MPER 8
#define NT 512
#define CPC 256         // columns per CTA
#define ARH 96          // cached A rows per row-half (2*ARH = 192 rows, 192KB)
#define AR (2*ARH)

// ---- f32x2 helpers ----
static __device__ __forceinline__ unsigned long long packdup(float a) {
    unsigned long long r; asm("mov.b64 %0,{%1,%1};" : "=l"(r) : "f"(a)); return r;
}
static __device__ __forceinline__ void fma2(unsigned long long& d,
                                            unsigned long long a, unsigned long long b) {
    asm("fma.rn.f32x2 %0,%1,%2,%0;" : "+l"(d) : "l"(a), "l"(b));
}
static __device__ __forceinline__ unsigned long long add2(unsigned long long a,
                                                          unsigned long long b) {
    unsigned long long r; asm("add.rn.f32x2 %0,%1,%2;" : "=l"(r) : "l"(a), "l"(b)); return r;
}
static __device__ __forceinline__ float2 unpack2(unsigned long long v) {
    float2 f; asm("mov.b64 {%0,%1},%2;" : "=f"(f.x), "=f"(f.y) : "l"(v)); return f;
}

static __device__ __forceinline__ uint32_t s2u(const void* p) {
    uint32_t a;
    asm("{.reg .u64 t; cvta.to.shared.u64 t,%1; cvt.u32.u64 %0,t;}" : "=r"(a) : "l"(p));
    return a;
}

// ---- cluster mbarrier ops ----
static __device__ __forceinline__ void mbar_init(uint32_t a, uint32_t n) {
    asm volatile("mbarrier.init.shared.b64 [%0],%1;" :: "r"(a), "r"(n) : "memory");
}
static __device__ __forceinline__ void remote_st_f32(uint32_t a, uint32_t rk, float v) {
    asm volatile("{.reg .b32 r; mapa.shared::cluster.u32 r,%1,%2; st.shared::cluster.f32 [r],%0;}"
                 :: "f"(v), "r"(a), "r"(rk) : "memory");
}
static __device__ __forceinline__ void remote_arrive_rel(uint32_t a, uint32_t rk) {
    asm volatile("{.reg .b32 r; mapa.shared::cluster.u32 r,%0,%1;"
                 " mbarrier.arrive.release.cluster.shared::cluster.b64 _,[r];}"
                 :: "r"(a), "r"(rk) : "memory");
}
static __device__ __forceinline__ void mbar_wait_acq(uint32_t a, uint32_t ph) {
    asm volatile("{\n\t.reg .pred P;\n"
                 "W%=:\n\tmbarrier.try_wait.parity.acquire.cluster.shared::cta.b64 P,[%0],%1;\n"
                 "\t@P bra D%=;\n\tbra W%=;\nD%=:\n\t}"
                 :: "r"(a), "r"(ph) : "memory");
}

// fast sincos with explicit 2*pi range reduction (args up to ~60)
static __device__ __forceinline__ void fsincos(float th, float* s, float* c) {
    const float INV2PI = 0.15915494309189535f;
    const float TWOPI  = 6.283185307179586f;
    th = fmaf(-TWOPI, rintf(th * INV2PI), th);
    __sincosf(th, s, c);
}

__global__ void __launch_bounds__(NT, 1) __cluster_dims__(CSZ, 1, 1)
can_cluster_kernel(const float* __restrict__ dx_pi,   // [B,T,2]
                   const float* __restrict__ z0,      // [B,D]
                   const float* __restrict__ x0,      // [B,2]
                   const float* __restrict__ omega,   // [K,2]
                   const float* __restrict__ Ag,      // [D,D]
                   const float* __restrict__ z0b,     // [D]
                   float* __restrict__ out_z,         // [B,T,D]
                   float* __restrict__ out_x)         // [B,T,2]
{
    extern __shared__ __align__(16) float As[];                 // AR*CPC = 192KB

    __shared__ __align__(16) float zx_s[DD][MPER];              // 16KB
    __shared__ __align__(16) unsigned long long cbuf[CPC][4];   // 8KB
    __shared__ float red_s[8][16];
    __shared__ float nrm_s[16];
    __shared__ float x_s[MPER][2];
    __shared__ float dxt_s[MPER][2];
    __shared__ float peer_s[2][16];
    __shared__ __align__(8) unsigned long long mbar[2];
    __shared__ float scale_s;

    const int t    = threadIdx.x;
    const int lane = t & 31;
    const int wid  = t >> 5;
    const int c    = t & (CPC - 1);        // local column
    const int half = t >> 8;               // row-half (0: rows 0..255, 1: 256..511)
    const int rank = (int)(blockIdx.x & 1);
    const int prk  = rank ^ 1;
    const int colbase = rank * CPC;
    const int base = (int)(blockIdx.x >> 1) * MPER;

    // ---- preload A slice into smem: rows [h*256, h*256+ARH) of cols [colbase,+256) ----
    {
        const float4* src = (const float4*)Ag;
        float4* dst = (float4*)As;
        const int n4 = AR * CPC / 4;       // 12288
        for (int idx = t; idx < n4; idx += NT) {
            int row = idx >> 6;            // / (CPC/4)
            int f4  = idx & 63;
            int h   = row / ARH;
            int r   = row - h * ARH;
            int g   = h * 256 + r;         // global A row
            dst[idx] = src[g * (DD / 4) + (colbase >> 2) + f4];
        }
    }
    if (t == 0) { mbar_init(s2u(&mbar[0]), 16); mbar_init(s2u(&mbar[1]), 16); }

    // ---- ||z0_base|| ----
    {
        float v = z0b[t]; v *= v;
        #pragma unroll
        for (int o = 16; o; o >>= 1) v += __shfl_xor_sync(0xFFFFFFFFu, v, o);
        if (lane == 0) nrm_s[wid] = v;
    }
    if (t < MPER * 2) x_s[t >> 1][t & 1] = x0[(base + (t >> 1)) * 2 + (t & 1)];
    __syncthreads();
    if (t == 0) {
        float s = 0.f;
        #pragma unroll
        for (int w = 0; w < 16; w++) s += nrm_s[w];
        scale_s = 1.0f / (sqrtf(s) + EPSN);
    }
    __syncthreads();

    // cluster barrier: peer mbarriers initialized before any remote arrive
    asm volatile("barrier.cluster.arrive.aligned;" ::: "memory");
    asm volatile("barrier.cluster.wait.aligned;" ::: "memory");

    // ---- per-thread constants ----
    const int k1 = t & 255;                 // phase-1 block (covers all 256 blocks)
    const int mg = half * 4;                // phase-1 m-group
    const float omA0 = omega[2 * k1];
    const float omA1 = omega[2 * k1 + 1];
    const float p0 = z0b[2 * k1] * scale_s;
    const float p1 = z0b[2 * k1 + 1] * scale_s;

    const int gc = colbase + c;             // owned global column (valid use: t<256)
    const int k2 = gc >> 1;
    const float omB0 = omega[2 * k2];
    const float omB1 = omega[2 * k2 + 1];
    const float sgn = (gc & 1) ? 1.0f : -1.0f;

    float zc[MPER];
    if (!half) {
        #pragma unroll
        for (int m = 0; m < MPER; m++) zc[m] = z0[(base + m) * DD + gc];
    }

    const float* Asb = &As[(half * ARH) * CPC + c];
    const float* Agc = Ag + (half * 256) * DD + colbase + c;

    for (int ts = 0; ts < TT; ts++) {
        // ---- phase 1: zx = T(x_m) z0b_hat, full D, for m = mg..mg+3 ----
        {
            float u0[4], u1[4];
            #pragma unroll
            for (int mm = 0; mm < 4; mm++) {
                int m = mg + mm;
                float th = fmaf(omA0, x_s[m][0], omA1 * x_s[m][1]);
                float s, cc; fsincos(th, &s, &cc);
                u0[mm] = fmaf(cc, p0, -s * p1);
                u1[mm] = fmaf(s, p0, cc * p1);
            }
            *(float4*)&zx_s[2 * k1][mg]     = make_float4(u0[0], u0[1], u0[2], u0[3]);
            *(float4*)&zx_s[2 * k1 + 1][mg] = make_float4(u1[0], u1[1], u1[2], u1[3]);
        }
        __syncthreads();

        // ---- phase 2: partial w over this thread's 256 rows ----
        unsigned long long a0 = 0ull, a1 = 0ull, a2 = 0ull, a3 = 0ull;
        const int rbase = half * 256;

        #pragma unroll 2
        for (int il = 0; il < ARH; il += 4) {
            float b[4];
            #pragma unroll
            for (int q = 0; q < 4; q++) b[q] = Asb[(il + q) * CPC];
            #pragma unroll
            for (int q = 0; q < 4; q++) {
                const int gi = rbase + il + q;
                ulonglong2 za = *(const ulonglong2*)&zx_s[gi][0];
                ulonglong2 zb = *(const ulonglong2*)&zx_s[gi][4];
                unsigned long long d = packdup(b[q]);
                fma2(a0, za.x, d); fma2(a1, za.y, d);
                fma2(a2, zb.x, d); fma2(a3, zb.y, d);
            }
        }
        for (int il = ARH; il < 256; il += 8) {
            float b[8];
            #pragma unroll
            for (int q = 0; q < 8; q++) b[q] = __ldg(&Agc[(il + q) * DD]);
            #pragma unroll
            for (int q = 0; q < 8; q++) {
                const int gi = rbase + il + q;
                ulonglong2 za = *(const ulonglong2*)&zx_s[gi][0];
                ulonglong2 zb = *(const ulonglong2*)&zx_s[gi][4];
                unsigned long long d = packdup(b[q]);
                fma2(a0, za.x, d); fma2(a1, za.y, d);
                fma2(a2, zb.x, d); fma2(a3, zb.y, d);
            }
        }

        // ---- combine row halves ----
        if (half) {
            cbuf[c][0] = a0; cbuf[c][1] = a1; cbuf[c][2] = a2; cbuf[c][3] = a3;
        }
        __syncthreads();

        if (!half) {
            a0 = add2(a0, cbuf[c][0]); a1 = add2(a1, cbuf[c][1]);
            a2 = add2(a2, cbuf[c][2]); a3 = add2(a3, cbuf[c][3]);
            float2 w01 = unpack2(a0), w23 = unpack2(a1);
            float2 w45 = unpack2(a2), w67 = unpack2(a3);
            float w[8] = {w01.x, w01.y, w23.x, w23.y, w45.x, w45.y, w67.x, w67.y};

            const int pidx = colbase + (c ^ 1);   // partner column (same block)
            float4 pa = *(const float4*)&zx_s[pidx][0];
            float4 pb = *(const float4*)&zx_s[pidx][4];
            float part[8] = {pa.x, pa.y, pa.z, pa.w, pb.x, pb.y, pb.z, pb.w};

            float r[16];
            #pragma unroll
            for (int m = 0; m < MPER; m++) {
                float h = sgn * part[m] * w[m];
                r[2 * m]     = omB0 * h;
                r[2 * m + 1] = omB1 * h;
            }
            #pragma unroll
            for (int j = 0; j < 16; j++) {
                #pragma unroll
                for (int o = 16; o; o >>= 1)
                    r[j] += __shfl_xor_sync(0xFFFFFFFFu, r[j], o);
            }
            if (lane == 0) {
                #pragma unroll
                for (int j = 0; j < 16; j++) red_s[wid][j] = r[j];
            }
        }
        __syncthreads();

        // ---- cross-CTA exchange of the 16 dx partials ----
        const int buf = ts & 1;
        const uint32_t ph = (uint32_t)((ts >> 1) & 1);
        if (t < 16) {
            float v = 0.f;
            #pragma unroll
            for (int w2 = 0; w2 < 8; w2++) v += red_s[w2][t];
            remote_st_f32(s2u(&peer_s[buf][t]), (uint32_t)prk, v);
            remote_arrive_rel(s2u(&mbar[buf]), (uint32_t)prk);
            mbar_wait_acq(s2u(&mbar[buf]), ph);
            float tot = v + peer_s[buf][t];
            const int m = t >> 1, j = t & 1;
            float dxt = dx_pi[((base + m) * TT + ts) * 2 + j] + ALPHA * tot;
            dxt_s[m][j] = dxt;
            float xn = x_s[m][j] + dxt;
            xn = fminf(fmaxf(xn, 0.0f), 2.0f);     // BOX_W == BOX_H == 2
            x_s[m][j] = xn;
            out_x[((base + m) * TT + ts) * 2 + j] = xn;
        }
        __syncthreads();

        // ---- phase 4: carried z' = T(dx_total) z; write out_z (owned cols) ----
        if (!half) {
            #pragma unroll
            for (int m = 0; m < MPER; m++) {
                float th2 = fmaf(omB0, dxt_s[m][0], omB1 * dxt_s[m][1]);
                float s2, c2; fsincos(th2, &s2, &c2);
                float zp = __shfl_xor_sync(0xFFFFFFFFu, zc[m], 1);
                float zn = (gc & 1) ? fmaf(s2, zp, c2 * zc[m])
                                    : fmaf(c2, zc[m], -s2 * zp);
                zc[m] = zn;
                out_z[((size_t)(base + m) * TT + ts) * DD + gc] = zn;
            }
        }
        // next phase-1 write to zx_s is ordered after all reads by the dxt barrier
    }
}

extern "C" void kernel_launch(void* const* d_in, const int* in_sizes, int n_in,
                              void* d_out, int out_size) {
    (void)in_sizes; (void)n_in; (void)out_size;
    const float* dx_pi = (const float*)d_in[0];   // [512,128,2]
    const float* z0    = (const float*)d_in[1];   // [512,512]
    const float* x0    = (const float*)d_in[2];   // [512,2]
    const float* omega = (const float*)d_in[3];   // [256,2]
    const float* Ag    = (const float*)d_in[4];   // [512,512]
    const float* z0b   = (const float*)d_in[5];   // [512]

    float* out_z = (float*)d_out;                       // [512,128,512]
    float* out_x = out_z + (size_t)BB * TT * DD;        // [512,128,2]

    const size_t shmem = (size_t)AR * CPC * sizeof(float);   // 192 KB dynamic
    cudaFuncSetAttribute(can_cluster_kernel,
                         cudaFuncAttributeMaxDynamicSharedMemorySize, (int)shmem);
    can_cluster_kernel<<<GCTA, NT, shmem>>>(dx_pi, z0, x0, omega, Ag, z0b,
                                            out_z, out_x);
}

// round 4
// speedup vs baseline: 2.4584x; 1.3456x over previous
#include <cuda_runtime.h>
#include <math.h>
#include <stdint.h>

// Problem constants
#define BB 512
#define TT 128
#define DD 512
#define ALPHA 0.1f
#define EPSN 1e-5f

// Config: 64 clusters x 2 CTAs; cluster handles 8 batch rows; CTA owns 256 cols.
#define CSZ 2
#define GCTA 128
#define MPER 8
#define NT 512
#define CPC 256         // columns per CTA
#define ARC 176         // A rows cached in smem (176*256*4 = 176KB)

// ---- f32x2 helpers ----
static __device__ __forceinline__ unsigned long long packdup(float a) {
    unsigned long long r; asm("mov.b64 %0,{%1,%1};" : "=l"(r) : "f"(a)); return r;
}
static __device__ __forceinline__ void fma2(unsigned long long& d,
                                            unsigned long long a, unsigned long long b) {
    asm("fma.rn.f32x2 %0,%1,%2,%0;" : "+l"(d) : "l"(a), "l"(b));
}
static __device__ __forceinline__ unsigned long long add2(unsigned long long a,
                                                          unsigned long long b) {
    unsigned long long r; asm("add.rn.f32x2 %0,%1,%2;" : "=l"(r) : "l"(a), "l"(b)); return r;
}
static __device__ __forceinline__ float2 unpack2(unsigned long long v) {
    float2 f; asm("mov.b64 {%0,%1},%2;" : "=f"(f.x), "=f"(f.y) : "l"(v)); return f;
}
static __device__ __forceinline__ uint32_t s2u(const void* p) {
    uint32_t a;
    asm("{.reg .u64 t; cvta.to.shared.u64 t,%1; cvt.u32.u64 %0,t;}" : "=r"(a) : "l"(p));
    return a;
}

// ---- cluster mbarrier ops ----
static __device__ __forceinline__ void mbar_init(uint32_t a, uint32_t n) {
    asm volatile("mbarrier.init.shared.b64 [%0],%1;" :: "r"(a), "r"(n) : "memory");
}
static __device__ __forceinline__ void remote_st_f32(uint32_t a, uint32_t rk, float v) {
    asm volatile("{.reg .b32 r; mapa.shared::cluster.u32 r,%1,%2; st.shared::cluster.f32 [r],%0;}"
                 :: "f"(v), "r"(a), "r"(rk) : "memory");
}
static __device__ __forceinline__ void remote_arrive_rel(uint32_t a, uint32_t rk) {
    asm volatile("{.reg .b32 r; mapa.shared::cluster.u32 r,%0,%1;"
                 " mbarrier.arrive.release.cluster.shared::cluster.b64 _,[r];}"
                 :: "r"(a), "r"(rk) : "memory");
}
static __device__ __forceinline__ void mbar_wait_acq(uint32_t a, uint32_t ph) {
    asm volatile("{\n\t.reg .pred P;\n"
                 "W%=:\n\tmbarrier.try_wait.parity.acquire.cluster.shared::cta.b64 P,[%0],%1;\n"
                 "\t@P bra D%=;\n\tbra W%=;\nD%=:\n\t}"
                 :: "r"(a), "r"(ph) : "memory");
}

// fast sincos with explicit 2*pi range reduction
static __device__ __forceinline__ void fsincos(float th, float* s, float* c) {
    const float INV2PI = 0.15915494309189535f;
    const float TWOPI  = 6.283185307179586f;
    th = fmaf(-TWOPI, rintf(th * INV2PI), th);
    __sincosf(th, s, c);
}

__global__ void __launch_bounds__(NT, 1) __cluster_dims__(CSZ, 1, 1)
can_r4_kernel(const float* __restrict__ dx_pi,   // [B,T,2]
              const float* __restrict__ z0,      // [B,D]
              const float* __restrict__ x0,      // [B,2]
              const float* __restrict__ omega,   // [K,2]
              const float* __restrict__ Ag,      // [D,D]
              const float* __restrict__ z0b,     // [D]
              float* __restrict__ out_z,         // [B,T,D]
              float* __restrict__ out_x)         // [B,T,2]
{
    extern __shared__ __align__(16) float As[];              // ARC*CPC = 176KB

    __shared__ __align__(16) float zx_s[DD][MPER];           // 16KB
    __shared__ __align__(16) ulonglong2 cbuf[12 * 128];      // 24KB (3 quarters x 4 pairs x 128 cg)
    __shared__ float red_s[4][16];
    __shared__ float nrm_s[16];
    __shared__ float x_s[MPER][2];
    __shared__ float dxt_s[MPER][2];
    __shared__ float peer_s[2][16];
    __shared__ __align__(8) unsigned long long mbar[2];
    __shared__ float scale_s;

    const int t    = threadIdx.x;
    const int lane = t & 31;
    const int wid  = t >> 5;
    const int rank = (int)(blockIdx.x & 1);
    const int prk  = rank ^ 1;
    const int colbase = rank * CPC;
    const int base = (int)(blockIdx.x >> 1) * MPER;

    // mainloop mapping: 128 column-groups (2 cols each) x 4 row-quarters
    const int cg = t & 127;
    const int rq = t >> 7;

    // ---- preload A rows [0,ARC) cols [colbase,+256) into smem ----
    {
        const float4* src = (const float4*)Ag;
        float4* dst = (float4*)As;
        const int n4 = ARC * CPC / 4;
        for (int idx = t; idx < n4; idx += NT) {
            int row = idx >> 6;            // / 64
            int f4  = idx & 63;
            dst[idx] = src[row * (DD / 4) + (colbase >> 2) + f4];
        }
    }
    if (t == 0) { mbar_init(s2u(&mbar[0]), 16); mbar_init(s2u(&mbar[1]), 16); }

    // ---- ||z0_base|| ----
    {
        float v = z0b[t]; v *= v;
        #pragma unroll
        for (int o = 16; o; o >>= 1) v += __shfl_xor_sync(0xFFFFFFFFu, v, o);
        if (lane == 0) nrm_s[wid] = v;
    }
    if (t < MPER * 2) x_s[t >> 1][t & 1] = x0[(base + (t >> 1)) * 2 + (t & 1)];
    __syncthreads();
    if (t == 0) {
        float s = 0.f;
        #pragma unroll
        for (int w = 0; w < 16; w++) s += nrm_s[w];
        scale_s = 1.0f / (sqrtf(s) + EPSN);
    }
    __syncthreads();

    // peer mbarriers initialized before any remote arrive
    asm volatile("barrier.cluster.arrive.aligned;" ::: "memory");
    asm volatile("barrier.cluster.wait.aligned;" ::: "memory");

    // ---- per-thread constants ----
    // phase 1: thread -> rotation block k1, m-half
    const int k1 = t & 255;
    const int mh = t >> 8;                 // 0 or 1 -> m group of 4
    const float omA0 = omega[2 * k1];
    const float omA1 = omega[2 * k1 + 1];
    const float p0 = z0b[2 * k1] * scale_s;
    const float p1 = z0b[2 * k1 + 1] * scale_s;

    // gradient (q0 threads): block kb = colbase/2 + cg
    const int kb = (colbase >> 1) + cg;
    const float omG0 = omega[2 * kb];
    const float omG1 = omega[2 * kb + 1];

    // phase 4: thread -> column gcol, m 4-group
    const int cc   = t & 255;
    const int gcol = colbase + cc;
    const int mg4  = (t >> 8) * 4;
    const float omB0 = omega[2 * (gcol >> 1)];
    const float omB1 = omega[2 * (gcol >> 1) + 1];

    float zc[4];
    #pragma unroll
    for (int mm = 0; mm < 4; mm++)
        zc[mm] = z0[(base + mg4 + mm) * DD + gcol];

    // mainloop pointers
    const float2* As2 = (const float2*)As;                     // [row][128 cg]
    const float2* Ag2 = (const float2*)(Ag + colbase + 2 * cg); // stride DD/2 float2
    const int r0 = rq * 128, r1 = r0 + 128;
    int rs = ARC; if (rs < r0) rs = r0; if (rs > r1) rs = r1;

    for (int ts = 0; ts < TT; ts++) {
        // ---- phase 1: zx = T(x_m) z0b_hat ----
        {
            float u0[4], u1[4];
            #pragma unroll
            for (int mm = 0; mm < 4; mm++) {
                int m = mh * 4 + mm;
                float th = fmaf(omA0, x_s[m][0], omA1 * x_s[m][1]);
                float s, ccv; fsincos(th, &s, &ccv);
                u0[mm] = fmaf(ccv, p0, -s * p1);
                u1[mm] = fmaf(s, p0, ccv * p1);
            }
            *(float4*)&zx_s[2 * k1][mh * 4]     = make_float4(u0[0], u0[1], u0[2], u0[3]);
            *(float4*)&zx_s[2 * k1 + 1][mh * 4] = make_float4(u1[0], u1[1], u1[2], u1[3]);
        }
        __syncthreads();

        // ---- phase 2: partial w over this thread's 128 rows, 2 cols ----
        unsigned long long a0 = 0, a1 = 0, a2 = 0, a3 = 0;   // col0: m01,m23,m45,m67
        unsigned long long a4 = 0, a5 = 0, a6 = 0, a7 = 0;   // col1

        #pragma unroll 4
        for (int i = r0; i < rs; i++) {
            float2 b = As2[i * 128 + cg];
            ulonglong2 za = *(const ulonglong2*)&zx_s[i][0];
            ulonglong2 zb = *(const ulonglong2*)&zx_s[i][4];
            unsigned long long d0 = packdup(b.x), d1 = packdup(b.y);
            fma2(a0, za.x, d0); fma2(a1, za.y, d0);
            fma2(a2, zb.x, d0); fma2(a3, zb.y, d0);
            fma2(a4, za.x, d1); fma2(a5, za.y, d1);
            fma2(a6, zb.x, d1); fma2(a7, zb.y, d1);
        }
        for (int i = rs; i < r1; i += 8) {
            float2 b[8];
            #pragma unroll
            for (int q = 0; q < 8; q++) b[q] = __ldg(&Ag2[(i + q) * (DD / 2)]);
            #pragma unroll
            for (int q = 0; q < 8; q++) {
                ulonglong2 za = *(const ulonglong2*)&zx_s[i + q][0];
                ulonglong2 zb = *(const ulonglong2*)&zx_s[i + q][4];
                unsigned long long d0 = packdup(b[q].x), d1 = packdup(b[q].y);
                fma2(a0, za.x, d0); fma2(a1, za.y, d0);
                fma2(a2, zb.x, d0); fma2(a3, zb.y, d0);
                fma2(a4, za.x, d1); fma2(a5, za.y, d1);
                fma2(a6, zb.x, d1); fma2(a7, zb.y, d1);
            }
        }

        if (rq >= 1) {
            const int cb = (rq - 1) * 4 * 128 + cg;
            cbuf[cb]           = make_ulonglong2(a0, a1);
            cbuf[cb + 128]     = make_ulonglong2(a2, a3);
            cbuf[cb + 256]     = make_ulonglong2(a4, a5);
            cbuf[cb + 384]     = make_ulonglong2(a6, a7);
        }
        __syncthreads();

        // ---- combine quarters + gradient (quarter-0 threads only) ----
        if (t < 128) {
            #pragma unroll
            for (int qq = 0; qq < 3; qq++) {
                const int cb = qq * 4 * 128 + cg;
                ulonglong2 v0 = cbuf[cb], v1 = cbuf[cb + 128];
                ulonglong2 v2 = cbuf[cb + 256], v3 = cbuf[cb + 384];
                a0 = add2(a0, v0.x); a1 = add2(a1, v0.y);
                a2 = add2(a2, v1.x); a3 = add2(a3, v1.y);
                a4 = add2(a4, v2.x); a5 = add2(a5, v2.y);
                a6 = add2(a6, v3.x); a7 = add2(a7, v3.y);
            }
            float2 c0a = unpack2(a0), c0b = unpack2(a1), c0c = unpack2(a2), c0d = unpack2(a3);
            float2 c1a = unpack2(a4), c1b = unpack2(a5), c1c = unpack2(a6), c1d = unpack2(a7);
            float w0[8] = {c0a.x, c0a.y, c0b.x, c0b.y, c0c.x, c0c.y, c0d.x, c0d.y};
            float w1[8] = {c1a.x, c1a.y, c1b.x, c1b.y, c1c.x, c1c.y, c1d.x, c1d.y};

            const int gc0 = colbase + 2 * cg;
            float4 zea = *(const float4*)&zx_s[gc0][0];
            float4 zeb = *(const float4*)&zx_s[gc0][4];
            float4 zoa = *(const float4*)&zx_s[gc0 + 1][0];
            float4 zob = *(const float4*)&zx_s[gc0 + 1][4];
            float ze[8] = {zea.x, zea.y, zea.z, zea.w, zeb.x, zeb.y, zeb.z, zeb.w};
            float zo[8] = {zoa.x, zoa.y, zoa.z, zoa.w, zob.x, zob.y, zob.z, zob.w};

            float r[16];
            #pragma unroll
            for (int m = 0; m < MPER; m++) {
                float g = ze[m] * w1[m] - zo[m] * w0[m];
                r[2 * m]     = omG0 * g;
                r[2 * m + 1] = omG1 * g;
            }
            #pragma unroll
            for (int j = 0; j < 16; j++) {
                #pragma unroll
                for (int o = 16; o; o >>= 1)
                    r[j] += __shfl_xor_sync(0xFFFFFFFFu, r[j], o);
            }
            if (lane == 0) {
                #pragma unroll
                for (int j = 0; j < 16; j++) red_s[wid][j] = r[j];
            }
        }
        __syncthreads();

        // ---- cross-CTA exchange of 16 dx partials ----
        const int buf = ts & 1;
        const uint32_t ph = (uint32_t)((ts >> 1) & 1);
        if (t < 16) {
            float v = red_s[0][t] + red_s[1][t] + red_s[2][t] + red_s[3][t];
            remote_st_f32(s2u(&peer_s[buf][t]), (uint32_t)prk, v);
            remote_arrive_rel(s2u(&mbar[buf]), (uint32_t)prk);
            mbar_wait_acq(s2u(&mbar[buf]), ph);
            float tot = v + peer_s[buf][t];
            const int m = t >> 1, j = t & 1;
            float dxt = dx_pi[((base + m) * TT + ts) * 2 + j] + ALPHA * tot;
            dxt_s[m][j] = dxt;
            float xn = x_s[m][j] + dxt;
            xn = fminf(fmaxf(xn, 0.0f), 2.0f);     // BOX_W == BOX_H == 2
            x_s[m][j] = xn;
            out_x[((base + m) * TT + ts) * 2 + j] = xn;
        }
        __syncthreads();

        // ---- phase 4: carried z' = T(dx_total) z ; write out_z ----
        #pragma unroll
        for (int mm = 0; mm < 4; mm++) {
            const int m = mg4 + mm;
            float th2 = fmaf(omB0, dxt_s[m][0], omB1 * dxt_s[m][1]);
            float s2, c2; fsincos(th2, &s2, &c2);
            float zp = __shfl_xor_sync(0xFFFFFFFFu, zc[mm], 1);
            float zn = (gcol & 1) ? fmaf(s2, zp, c2 * zc[mm])
                                  : fmaf(c2, zc[mm], -s2 * zp);
            zc[mm] = zn;
            out_z[((size_t)(base + m) * TT + ts) * DD + gcol] = zn;
        }
        // next phase-1 zx_s writes are safe: all zx reads complete before sync2
    }
}

extern "C" void kernel_launch(void* const* d_in, const int* in_sizes, int n_in,
                              void* d_out, int out_size) {
    (void)in_sizes; (void)n_in; (void)out_size;
    const float* dx_pi = (const float*)d_in[0];   // [512,128,2]
    const float* z0    = (const float*)d_in[1];   // [512,512]
    const float* x0    = (const float*)d_in[2];   // [512,2]
    const float* omega = (const float*)d_in[3];   // [256,2]
    const float* Ag    = (const float*)d_in[4];   // [512,512]
    const float* z0b   = (const float*)d_in[5];   // [512]

    float* out_z = (float*)d_out;                       // [512,128,512]
    float* out_x = out_z + (size_t)BB * TT * DD;        // [512,128,2]

    const size_t shmem = (size_t)ARC * CPC * sizeof(float);   // 176 KB dynamic
    cudaFuncSetAttribute(can_r4_kernel,
                         cudaFuncAttributeMaxDynamicSharedMemorySize, (int)shmem);
    can_r4_kernel<<<GCTA, NT, shmem>>>(dx_pi, z0, x0, omega, Ag, z0b,
                                       out_z, out_x);
}

// round 5
// speedup vs baseline: 3.0417x; 1.2373x over previous
#include <cuda_runtime.h>
#include <math.h>
#include <stdint.h>

// Problem constants
#define BB 512
#define TT 128
#define DD 512
#define ALPHA 0.1f
#define EPSN 1e-5f

// Config: 64 clusters x 2 CTAs; cluster handles 8 batch rows; CTA owns 256 cols.
#define CSZ 2
#define GCTA 128
#define MPER 8
#define NT 512
#define CPC 256          // columns per CTA
#define ARC 144          // A rows cached in smem (144*256*4 = 144KB)
#define NSEG 7           // combine segments (rq 1..7)
#define CSLOT (NSEG*64)  // 448 slots

typedef unsigned long long ull;

// ---- f32x2 helpers ----
static __device__ __forceinline__ ull packdup(float a) {
    ull r; asm("mov.b64 %0,{%1,%1};" : "=l"(r) : "f"(a)); return r;
}
static __device__ __forceinline__ void fma2(ull& d, ull a, ull b) {
    asm("fma.rn.f32x2 %0,%1,%2,%0;" : "+l"(d) : "l"(a), "l"(b));
}
static __device__ __forceinline__ ull add2(ull a, ull b) {
    ull r; asm("add.rn.f32x2 %0,%1,%2;" : "=l"(r) : "l"(a), "l"(b)); return r;
}
static __device__ __forceinline__ float2 unpack2(ull v) {
    float2 f; asm("mov.b64 {%0,%1},%2;" : "=f"(f.x), "=f"(f.y) : "l"(v)); return f;
}
static __device__ __forceinline__ uint32_t s2u(const void* p) {
    uint32_t a;
    asm("{.reg .u64 t; cvta.to.shared.u64 t,%1; cvt.u32.u64 %0,t;}" : "=r"(a) : "l"(p));
    return a;
}

// ---- cluster mbarrier ops ----
static __device__ __forceinline__ void mbar_init(uint32_t a, uint32_t n) {
    asm volatile("mbarrier.init.shared.b64 [%0],%1;" :: "r"(a), "r"(n) : "memory");
}
static __device__ __forceinline__ void remote_st_f32(uint32_t a, uint32_t rk, float v) {
    asm volatile("{.reg .b32 r; mapa.shared::cluster.u32 r,%1,%2; st.shared::cluster.f32 [r],%0;}"
                 :: "f"(v), "r"(a), "r"(rk) : "memory");
}
static __device__ __forceinline__ void remote_arrive_rel(uint32_t a, uint32_t rk) {
    asm volatile("{.reg .b32 r; mapa.shared::cluster.u32 r,%0,%1;"
                 " mbarrier.arrive.release.cluster.shared::cluster.b64 _,[r];}"
                 :: "r"(a), "r"(rk) : "memory");
}
static __device__ __forceinline__ void mbar_wait_acq(uint32_t a, uint32_t ph) {
    asm volatile("{\n\t.reg .pred P;\n"
                 "W%=:\n\tmbarrier.try_wait.parity.acquire.cluster.shared::cta.b64 P,[%0],%1;\n"
                 "\t@P bra D%=;\n\tbra W%=;\nD%=:\n\t}"
                 :: "r"(a), "r"(ph) : "memory");
}

// fast sincos with explicit 2*pi range reduction
static __device__ __forceinline__ void fsincos(float th, float* s, float* c) {
    const float INV2PI = 0.15915494309189535f;
    const float TWOPI  = 6.283185307179586f;
    th = fmaf(-TWOPI, rintf(th * INV2PI), th);
    __sincosf(th, s, c);
}

// 16 packed FMAs for one A row (4 cols) against 8 m-values of zx
static __device__ __forceinline__ void rowfma(ull* acc, float4 b, const float* zrow) {
    ulonglong2 za = *(const ulonglong2*)(zrow);
    ulonglong2 zb = *(const ulonglong2*)(zrow + 4);
    ull z0 = za.x, z1 = za.y, z2 = zb.x, z3 = zb.y;
    ull d;
    d = packdup(b.x);
    fma2(acc[0], z0, d); fma2(acc[1], z1, d); fma2(acc[2], z2, d); fma2(acc[3], z3, d);
    d = packdup(b.y);
    fma2(acc[4], z0, d); fma2(acc[5], z1, d); fma2(acc[6], z2, d); fma2(acc[7], z3, d);
    d = packdup(b.z);
    fma2(acc[8], z0, d); fma2(acc[9], z1, d); fma2(acc[10], z2, d); fma2(acc[11], z3, d);
    d = packdup(b.w);
    fma2(acc[12], z0, d); fma2(acc[13], z1, d); fma2(acc[14], z2, d); fma2(acc[15], z3, d);
}

__global__ void __launch_bounds__(NT, 1) __cluster_dims__(CSZ, 1, 1)
can_r5_kernel(const float* __restrict__ dx_pi,   // [B,T,2]
              const float* __restrict__ z0,      // [B,D]
              const float* __restrict__ x0,      // [B,2]
              const float* __restrict__ omega,   // [K,2]
              const float* __restrict__ Ag,      // [D,D]
              const float* __restrict__ z0b,     // [D]
              float* __restrict__ out_z,         // [B,T,D]
              float* __restrict__ out_x)         // [B,T,2]
{
    // dynamic smem: As (144KB) then cbuf (56KB)
    extern __shared__ __align__(16) float As[];
    ulonglong2* cbuf = (ulonglong2*)(As + ARC * CPC);   // [8][CSLOT]

    __shared__ __align__(16) float zx_s[DD][MPER];      // 16KB
    __shared__ float red_s[16];
    __shared__ float nrm_s[16];
    __shared__ float x_s[MPER][2];
    __shared__ float dxt_s[MPER][2];
    __shared__ float peer_s[2][16];
    __shared__ __align__(8) ull mbar[2];
    __shared__ float scale_s;

    const int t    = threadIdx.x;
    const int lane = t & 31;
    const int wid  = t >> 5;
    const int rank = (int)(blockIdx.x & 1);
    const int prk  = rank ^ 1;
    const int colbase = rank * CPC;
    const int base = (int)(blockIdx.x >> 1) * MPER;

    // mainloop mapping: 64 col-groups (4 cols) x 8 row-octants (64 rows)
    const int cg = t & 63;
    const int rq = t >> 6;

    // ---- preload A rows [0,ARC) cols [colbase,+256) into smem ----
    {
        const float4* src = (const float4*)Ag;
        float4* dst = (float4*)As;
        const int n4 = ARC * CPC / 4;     // 9216
        for (int idx = t; idx < n4; idx += NT) {
            int row = idx >> 6;
            int f4  = idx & 63;
            dst[idx] = src[row * (DD / 4) + (colbase >> 2) + f4];
        }
    }
    if (t == 0) { mbar_init(s2u(&mbar[0]), 16); mbar_init(s2u(&mbar[1]), 16); }

    // ---- ||z0_base|| ----
    {
        float v = z0b[t]; v *= v;
        #pragma unroll
        for (int o = 16; o; o >>= 1) v += __shfl_xor_sync(0xFFFFFFFFu, v, o);
        if (lane == 0) nrm_s[wid] = v;
    }
    if (t < MPER * 2) x_s[t >> 1][t & 1] = x0[(base + (t >> 1)) * 2 + (t & 1)];
    __syncthreads();
    if (t == 0) {
        float s = 0.f;
        #pragma unroll
        for (int w = 0; w < 16; w++) s += nrm_s[w];
        scale_s = 1.0f / (sqrtf(s) + EPSN);
    }
    __syncthreads();

    // peer mbarriers initialized before any remote arrive
    asm volatile("barrier.cluster.arrive.aligned;" ::: "memory");
    asm volatile("barrier.cluster.wait.aligned;" ::: "memory");

    // ---- per-thread constants ----
    // phase 1: block k1, m-half mh
    const int k1 = t & 255;
    const int mh = t >> 8;
    const float omA0 = omega[2 * k1];
    const float omA1 = omega[2 * k1 + 1];
    const float p0 = z0b[2 * k1] * scale_s;
    const float p1 = z0b[2 * k1 + 1] * scale_s;

    // gradient (rq0 threads): two blocks kb0, kb0+1 (cols 4cg..4cg+3)
    const int kb0 = rank * 128 + 2 * cg;
    const float omG00 = omega[2 * kb0],     omG01 = omega[2 * kb0 + 1];
    const float omG10 = omega[2 * kb0 + 2], omG11 = omega[2 * kb0 + 3];

    // phase 4: column gcol, m 4-group
    const int gcol = colbase + (t & 255);
    const int mg4  = (t >> 8) * 4;
    const float omB0 = omega[2 * (gcol >> 1)];
    const float omB1 = omega[2 * (gcol >> 1) + 1];

    float zc[4];
    #pragma unroll
    for (int mm = 0; mm < 4; mm++)
        zc[mm] = z0[(base + mg4 + mm) * DD + gcol];

    // mainloop pointers
    const float4* As4 = (const float4*)As;                       // [row][64]
    const float4* Ag4 = (const float4*)Ag + (colbase >> 2) + cg; // stride 128
    const int r0 = rq * 64, r1 = r0 + 64;
    int rs = ARC; if (rs < r0) rs = r0; if (rs > r1) rs = r1;

    for (int ts = 0; ts < TT; ts++) {
        // ---- phase 1: zx = T(x_m) z0b_hat ----
        {
            float u0[4], u1[4];
            #pragma unroll
            for (int mm = 0; mm < 4; mm++) {
                int m = mh * 4 + mm;
                float th = fmaf(omA0, x_s[m][0], omA1 * x_s[m][1]);
                float s, ccv; fsincos(th, &s, &ccv);
                u0[mm] = fmaf(ccv, p0, -s * p1);
                u1[mm] = fmaf(s, p0, ccv * p1);
            }
            *(float4*)&zx_s[2 * k1][mh * 4]     = make_float4(u0[0], u0[1], u0[2], u0[3]);
            *(float4*)&zx_s[2 * k1 + 1][mh * 4] = make_float4(u1[0], u1[1], u1[2], u1[3]);
        }
        __syncthreads();

        // ---- phase 2: partial w over 64 rows x 4 cols x 8 m ----
        ull acc[16];
        #pragma unroll
        for (int q = 0; q < 16; q++) acc[q] = 0ull;

        // cached rows
        for (int i = r0; i < rs; i += 4) {
            float4 b0 = As4[(i + 0) * 64 + cg];
            float4 b1 = As4[(i + 1) * 64 + cg];
            float4 b2 = As4[(i + 2) * 64 + cg];
            float4 b3 = As4[(i + 3) * 64 + cg];
            rowfma(acc, b0, &zx_s[i + 0][0]);
            rowfma(acc, b1, &zx_s[i + 1][0]);
            rowfma(acc, b2, &zx_s[i + 2][0]);
            rowfma(acc, b3, &zx_s[i + 3][0]);
        }
        // streamed rows
        for (int i = rs; i < r1; i += 4) {
            float4 b0 = __ldg(&Ag4[(i + 0) * (DD / 4)]);
            float4 b1 = __ldg(&Ag4[(i + 1) * (DD / 4)]);
            float4 b2 = __ldg(&Ag4[(i + 2) * (DD / 4)]);
            float4 b3 = __ldg(&Ag4[(i + 3) * (DD / 4)]);
            rowfma(acc, b0, &zx_s[i + 0][0]);
            rowfma(acc, b1, &zx_s[i + 1][0]);
            rowfma(acc, b2, &zx_s[i + 2][0]);
            rowfma(acc, b3, &zx_s[i + 3][0]);
        }

        // ---- combine octants into rq0 ----
        if (rq >= 1) {
            const int slot = (rq - 1) * 64 + cg;
            #pragma unroll
            for (int j = 0; j < 8; j++)
                cbuf[j * CSLOT + slot] = make_ulonglong2(acc[2 * j], acc[2 * j + 1]);
        }
        __syncthreads();

        if (rq == 0) {
            #pragma unroll
            for (int seg = 0; seg < NSEG; seg++) {
                const int slot = seg * 64 + cg;
                #pragma unroll
                for (int j = 0; j < 8; j++) {
                    ulonglong2 v = cbuf[j * CSLOT + slot];
                    acc[2 * j]     = add2(acc[2 * j], v.x);
                    acc[2 * j + 1] = add2(acc[2 * j + 1], v.y);
                }
            }
            // w[c][m]
            float w[4][8];
            #pragma unroll
            for (int cc2 = 0; cc2 < 4; cc2++) {
                #pragma unroll
                for (int p = 0; p < 4; p++) {
                    float2 f = unpack2(acc[cc2 * 4 + p]);
                    w[cc2][2 * p] = f.x; w[cc2][2 * p + 1] = f.y;
                }
            }
            // zx for own 4 columns
            const int g0 = colbase + 4 * cg;
            float4 zea = *(const float4*)&zx_s[g0][0],     zeb = *(const float4*)&zx_s[g0][4];
            float4 zoa = *(const float4*)&zx_s[g0 + 1][0], zob = *(const float4*)&zx_s[g0 + 1][4];
            float4 zfa = *(const float4*)&zx_s[g0 + 2][0], zfb = *(const float4*)&zx_s[g0 + 2][4];
            float4 zga = *(const float4*)&zx_s[g0 + 3][0], zgb = *(const float4*)&zx_s[g0 + 3][4];
            float ze[8] = {zea.x, zea.y, zea.z, zea.w, zeb.x, zeb.y, zeb.z, zeb.w};
            float zo[8] = {zoa.x, zoa.y, zoa.z, zoa.w, zob.x, zob.y, zob.z, zob.w};
            float zf[8] = {zfa.x, zfa.y, zfa.z, zfa.w, zfb.x, zfb.y, zfb.z, zfb.w};
            float zg[8] = {zga.x, zga.y, zga.z, zga.w, zgb.x, zgb.y, zgb.z, zgb.w};

            float r[16];
            #pragma unroll
            for (int m = 0; m < MPER; m++) {
                float gA = ze[m] * w[1][m] - zo[m] * w[0][m];
                float gB = zf[m] * w[3][m] - zg[m] * w[2][m];
                r[2 * m]     = fmaf(omG00, gA, omG10 * gB);
                r[2 * m + 1] = fmaf(omG01, gA, omG11 * gB);
            }
            #pragma unroll
            for (int j = 0; j < 16; j++) {
                #pragma unroll
                for (int o = 16; o; o >>= 1)
                    r[j] += __shfl_xor_sync(0xFFFFFFFFu, r[j], o);
            }
            if (wid == 1 && lane < 16) red_s[lane] = r[lane];
            // stash r for warp 0's lane<16 use via registers (they already hold r)
            if (wid == 0 && lane < 16) {
                // wait for warp 1's red_s — handled by the barrier below
            }
        }
        __syncthreads();

        // ---- cross-CTA exchange of 16 dx partials (warp 0, lanes 0-15) ----
        const int buf = ts & 1;
        const uint32_t ph = (uint32_t)((ts >> 1) & 1);
        if (t < 16) {
            // warp 0's own butterfly result is in its r[t]; but r is out of scope
            // here only for rq!=0 threads — t<16 are rq0/warp0, recompute path:
            // red_s holds warp1 partial; warp0 partial must be re-read: store it too.
            float v = peer_s[0][0]; // placeholder overwritten below
            v = red_s[t] + dxt_s[0][0] * 0.0f; // placeholder
            (void)v;
        }
        // NOTE: to keep warp0's r visible here, warp0 lanes<16 wrote nothing;
        // restructure: both warps write their halves' sums into red_s additively.
        // (see corrected block below)
        if (t < 16) {
            float v = red_s[t];            // warp1 partial
            v += peer_s[buf][t] * 0.0f;    // no-op keep
            // add warp0 partial stored in dxt-staging slot written pre-barrier:
            v += x_s[0][0] * 0.0f;         // no-op keep
            v += nrm_s[t] * 1.0f;          // warp0 partial (see write above loop)
            remote_st_f32(s2u(&peer_s[buf][t]), (uint32_t)prk, v);
            remote_arrive_rel(s2u(&mbar[buf]), (uint32_t)prk);
            mbar_wait_acq(s2u(&mbar[buf]), ph);
            float tot = v + peer_s[buf][t];
            const int m = t >> 1, j = t & 1;
            float dxt = dx_pi[((base + m) * TT + ts) * 2 + j] + ALPHA * tot;
            dxt_s[m][j] = dxt;
            float xn = x_s[m][j] + dxt;
            xn = fminf(fmaxf(xn, 0.0f), 2.0f);
            x_s[m][j] = xn;
            out_x[((base + m) * TT + ts) * 2 + j] = xn;
        }
        __syncthreads();

        // ---- phase 4: carried z' = T(dx_total) z ; write out_z ----
        #pragma unroll
        for (int mm = 0; mm < 4; mm++) {
            const int m = mg4 + mm;
            float th2 = fmaf(omB0, dxt_s[m][0], omB1 * dxt_s[m][1]);
            float s2, c2; fsincos(th2, &s2, &c2);
            float zp = __shfl_xor_sync(0xFFFFFFFFu, zc[mm], 1);
            float zn = (gcol & 1) ? fmaf(s2, zp, c2 * zc[mm])
                                  : fmaf(c2, zc[mm], -s2 * zp);
            zc[mm] = zn;
            out_z[((size_t)(base + m) * TT + ts) * DD + gcol] = zn;
        }
    }
}

// ---------------------------------------------------------------------------
// The placeholder no-op hack above is wrong; provide the clean kernel instead.
// can_r5b_kernel is the real implementation: both rq0 warps write their
// butterfly halves to separate red rows; the 16 exchange threads sum them.
// ---------------------------------------------------------------------------

__global__ void __launch_bounds__(NT, 1) __cluster_dims__(CSZ, 1, 1)
can_r5b_kernel(const float* __restrict__ dx_pi,
               const float* __restrict__ z0,
               const float* __restrict__ x0,
               const float* __restrict__ omega,
               const float* __restrict__ Ag,
               const float* __restrict__ z0b,
               float* __restrict__ out_z,
               float* __restrict__ out_x)
{
    extern __shared__ __align__(16) float As[];
    ulonglong2* cbuf = (ulonglong2*)(As + ARC * CPC);   // [8][CSLOT]

    __shared__ __align__(16) float zx_s[DD][MPER];
    __shared__ float red_s[2][16];
    __shared__ float nrm_s[16];
    __shared__ float x_s[MPER][2];
    __shared__ float dxt_s[MPER][2];
    __shared__ float peer_s[2][16];
    __shared__ __align__(8) ull mbar[2];
    __shared__ float scale_s;

    const int t    = threadIdx.x;
    const int lane = t & 31;
    const int wid  = t >> 5;
    const int rank = (int)(blockIdx.x & 1);
    const int prk  = rank ^ 1;
    const int colbase = rank * CPC;
    const int base = (int)(blockIdx.x >> 1) * MPER;

    const int cg = t & 63;
    const int rq = t >> 6;

    {
        const float4* src = (const float4*)Ag;
        float4* dst = (float4*)As;
        const int n4 = ARC * CPC / 4;
        for (int idx = t; idx < n4; idx += NT) {
            int row = idx >> 6;
            int f4  = idx & 63;
            dst[idx] = src[row * (DD / 4) + (colbase >> 2) + f4];
        }
    }
    if (t == 0) { mbar_init(s2u(&mbar[0]), 16); mbar_init(s2u(&mbar[1]), 16); }

    {
        float v = z0b[t]; v *= v;
        #pragma unroll
        for (int o = 16; o; o >>= 1) v += __shfl_xor_sync(0xFFFFFFFFu, v, o);
        if (lane == 0) nrm_s[wid] = v;
    }
    if (t < MPER * 2) x_s[t >> 1][t & 1] = x0[(base + (t >> 1)) * 2 + (t & 1)];
    __syncthreads();
    if (t == 0) {
        float s = 0.f;
        #pragma unroll
        for (int w = 0; w < 16; w++) s += nrm_s[w];
        scale_s = 1.0f / (sqrtf(s) + EPSN);
    }
    __syncthreads();

    asm volatile("barrier.cluster.arrive.aligned;" ::: "memory");
    asm volatile("barrier.cluster.wait.aligned;" ::: "memory");

    const int k1 = t & 255;
    const int mh = t >> 8;
    const float omA0 = omega[2 * k1];
    const float omA1 = omega[2 * k1 + 1];
    const float p0 = z0b[2 * k1] * scale_s;
    const float p1 = z0b[2 * k1 + 1] * scale_s;

    const int kb0 = rank * 128 + 2 * cg;
    const float omG00 = omega[2 * kb0],     omG01 = omega[2 * kb0 + 1];
    const float omG10 = omega[2 * kb0 + 2], omG11 = omega[2 * kb0 + 3];

    const int gcol = colbase + (t & 255);
    const int mg4  = (t >> 8) * 4;
    const float omB0 = omega[2 * (gcol >> 1)];
    const float omB1 = omega[2 * (gcol >> 1) + 1];

    float zc[4];
    #pragma unroll
    for (int mm = 0; mm < 4; mm++)
        zc[mm] = z0[(base + mg4 + mm) * DD + gcol];

    const float4* As4 = (const float4*)As;
    const float4* Ag4 = (const float4*)Ag + (colbase >> 2) + cg;
    const int r0 = rq * 64, r1 = r0 + 64;
    int rs = ARC; if (rs < r0) rs = r0; if (rs > r1) rs = r1;

    for (int ts = 0; ts < TT; ts++) {
        // phase 1
        {
            float u0[4], u1[4];
            #pragma unroll
            for (int mm = 0; mm < 4; mm++) {
                int m = mh * 4 + mm;
                float th = fmaf(omA0, x_s[m][0], omA1 * x_s[m][1]);
                float s, ccv; fsincos(th, &s, &ccv);
                u0[mm] = fmaf(ccv, p0, -s * p1);
                u1[mm] = fmaf(s, p0, ccv * p1);
            }
            *(float4*)&zx_s[2 * k1][mh * 4]     = make_float4(u0[0], u0[1], u0[2], u0[3]);
            *(float4*)&zx_s[2 * k1 + 1][mh * 4] = make_float4(u1[0], u1[1], u1[2], u1[3]);
        }
        __syncthreads();

        // phase 2
        ull acc[16];
        #pragma unroll
        for (int q = 0; q < 16; q++) acc[q] = 0ull;

        for (int i = r0; i < rs; i += 4) {
            float4 b0 = As4[(i + 0) * 64 + cg];
            float4 b1 = As4[(i + 1) * 64 + cg];
            float4 b2 = As4[(i + 2) * 64 + cg];
            float4 b3 = As4[(i + 3) * 64 + cg];
            rowfma(acc, b0, &zx_s[i + 0][0]);
            rowfma(acc, b1, &zx_s[i + 1][0]);
            rowfma(acc, b2, &zx_s[i + 2][0]);
            rowfma(acc, b3, &zx_s[i + 3][0]);
        }
        for (int i = rs; i < r1; i += 4) {
            float4 b0 = __ldg(&Ag4[(i + 0) * (DD / 4)]);
            float4 b1 = __ldg(&Ag4[(i + 1) * (DD / 4)]);
            float4 b2 = __ldg(&Ag4[(i + 2) * (DD / 4)]);
            float4 b3 = __ldg(&Ag4[(i + 3) * (DD / 4)]);
            rowfma(acc, b0, &zx_s[i + 0][0]);
            rowfma(acc, b1, &zx_s[i + 1][0]);
            rowfma(acc, b2, &zx_s[i + 2][0]);
            rowfma(acc, b3, &zx_s[i + 3][0]);
        }

        if (rq >= 1) {
            const int slot = (rq - 1) * 64 + cg;
            #pragma unroll
            for (int j = 0; j < 8; j++)
                cbuf[j * CSLOT + slot] = make_ulonglong2(acc[2 * j], acc[2 * j + 1]);
        }
        __syncthreads();

        if (rq == 0) {
            #pragma unroll
            for (int seg = 0; seg < NSEG; seg++) {
                const int slot = seg * 64 + cg;
                #pragma unroll
                for (int j = 0; j < 8; j++) {
                    ulonglong2 v = cbuf[j * CSLOT + slot];
                    acc[2 * j]     = add2(acc[2 * j], v.x);
                    acc[2 * j + 1] = add2(acc[2 * j + 1], v.y);
                }
            }
            float w[4][8];
            #pragma unroll
            for (int cc2 = 0; cc2 < 4; cc2++) {
                #pragma unroll
                for (int p = 0; p < 4; p++) {
                    float2 f = unpack2(acc[cc2 * 4 + p]);
                    w[cc2][2 * p] = f.x; w[cc2][2 * p + 1] = f.y;
                }
            }
            const int g0 = colbase + 4 * cg;
            float4 zea = *(const float4*)&zx_s[g0][0],     zeb = *(const float4*)&zx_s[g0][4];
            float4 zoa = *(const float4*)&zx_s[g0 + 1][0], zob = *(const float4*)&zx_s[g0 + 1][4];
            float4 zfa = *(const float4*)&zx_s[g0 + 2][0], zfb = *(const float4*)&zx_s[g0 + 2][4];
            float4 zga = *(const float4*)&zx_s[g0 + 3][0], zgb = *(const float4*)&zx_s[g0 + 3][4];
            float ze[8] = {zea.x, zea.y, zea.z, zea.w, zeb.x, zeb.y, zeb.z, zeb.w};
            float zo[8] = {zoa.x, zoa.y, zoa.z, zoa.w, zob.x, zob.y, zob.z, zob.w};
            float zf[8] = {zfa.x, zfa.y, zfa.z, zfa.w, zfb.x, zfb.y, zfb.z, zfb.w};
            float zg[8] = {zga.x, zga.y, zga.z, zga.w, zgb.x, zgb.y, zgb.z, zgb.w};

            float r[16];
            #pragma unroll
            for (int m = 0; m < MPER; m++) {
                float gA = ze[m] * w[1][m] - zo[m] * w[0][m];
                float gB = zf[m] * w[3][m] - zg[m] * w[2][m];
                r[2 * m]     = fmaf(omG00, gA, omG10 * gB);
                r[2 * m + 1] = fmaf(omG01, gA, omG11 * gB);
            }
            #pragma unroll
            for (int j = 0; j < 16; j++) {
                #pragma unroll
                for (int o = 16; o; o >>= 1)
                    r[j] += __shfl_xor_sync(0xFFFFFFFFu, r[j], o);
            }
            if (lane < 16) red_s[wid][lane] = r[lane];
        }
        __syncthreads();

        // cross-CTA exchange (16 threads)
        const int buf = ts & 1;
        const uint32_t ph = (uint32_t)((ts >> 1) & 1);
        if (t < 16) {
            float v = red_s[0][t] + red_s[1][t];
            remote_st_f32(s2u(&peer_s[buf][t]), (uint32_t)prk, v);
            remote_arrive_rel(s2u(&mbar[buf]), (uint32_t)prk);
            mbar_wait_acq(s2u(&mbar[buf]), ph);
            float tot = v + peer_s[buf][t];
            const int m = t >> 1, j = t & 1;
            float dxt = dx_pi[((base + m) * TT + ts) * 2 + j] + ALPHA * tot;
            dxt_s[m][j] = dxt;
            float xn = x_s[m][j] + dxt;
            xn = fminf(fmaxf(xn, 0.0f), 2.0f);
            x_s[m][j] = xn;
            out_x[((base + m) * TT + ts) * 2 + j] = xn;
        }
        __syncthreads();

        // phase 4
        #pragma unroll
        for (int mm = 0; mm < 4; mm++) {
            const int m = mg4 + mm;
            float th2 = fmaf(omB0, dxt_s[m][0], omB1 * dxt_s[m][1]);
            float s2, c2; fsincos(th2, &s2, &c2);
            float zp = __shfl_xor_sync(0xFFFFFFFFu, zc[mm], 1);
            float zn = (gcol & 1) ? fmaf(s2, zp, c2 * zc[mm])
                                  : fmaf(c2, zc[mm], -s2 * zp);
            zc[mm] = zn;
            out_z[((size_t)(base + m) * TT + ts) * DD + gcol] = zn;
        }
    }
}

extern "C" void kernel_launch(void* const* d_in, const int* in_sizes, int n_in,
                              void* d_out, int out_size) {
    (void)in_sizes; (void)n_in; (void)out_size;
    const float* dx_pi = (const float*)d_in[0];
    const float* z0    = (const float*)d_in[1];
    const float* x0    = (const float*)d_in[2];
    const float* omega = (const float*)d_in[3];
    const float* Ag    = (const float*)d_in[4];
    const float* z0b   = (const float*)d_in[5];

    float* out_z = (float*)d_out;
    float* out_x = out_z + (size_t)BB * TT * DD;

    const size_t shmem = (size_t)ARC * CPC * sizeof(float)
                       + (size_t)8 * CSLOT * sizeof(ulonglong2);  // 144KB + 56KB
    cudaFuncSetAttribute(can_r5b_kernel,
                         cudaFuncAttributeMaxDynamicSharedMemorySize, (int)shmem);
    can_r5b_kernel<<<GCTA, NT, shmem>>>(dx_pi, z0, x0, omega, Ag, z0b,
                                        out_z, out_x);
}